// round 15
// baseline (speedup 1.0000x reference)
#include <cuda_runtime.h>
#include <cuda_bf16.h>
#include <cstdint>

#define NB 2
#define T  16
#define C  64
#define H  128
#define W  128
#define HW (H*W)

typedef __nv_bfloat16 bf16;

// ---------------- scratch (no allocation allowed) ----------------
// activations: pixel-row-major, 128 bf16/pixel = [hi ch0..63 | lo ch0..63]
__device__ __align__(16) bf16 g_fbuf[(size_t)NB*H*W*128];   // 1x1-conv out (conv1 in)
__device__ __align__(16) bf16 g_hbuf[(size_t)NB*H*W*128];   // conv1 out (conv2 in)
__device__ float g_wfc_t[3*C*C];                            // [192][64] fp32
// conv weights pre-arranged in mma B-fragment order:
// [s][j(12)][np(4)][lane(32)] -> uint4 {b0_f(2np), b1_f(2np), b0_f(2np+1), b1_f(2np+1)}
__device__ uint4 g_w1fr[9*12*4*32];
__device__ uint4 g_w2fr[9*12*4*32];

// ---------------- helpers ----------------
__device__ __forceinline__ uint32_t smem_u32(const void* p) {
    uint32_t a;
    asm("{ .reg .u64 t; cvta.to.shared.u64 t, %1; cvt.u32.u64 %0, t; }" : "=r"(a) : "l"(p));
    return a;
}
__device__ __forceinline__ void ldsm4(uint32_t& r0, uint32_t& r1, uint32_t& r2, uint32_t& r3,
                                      uint32_t addr) {
    asm volatile("ldmatrix.sync.aligned.m8n8.x4.shared.b16 {%0,%1,%2,%3}, [%4];"
                 : "=r"(r0), "=r"(r1), "=r"(r2), "=r"(r3) : "r"(addr));
}
__device__ __forceinline__ void mma16816(float* d,
        uint32_t a0, uint32_t a1, uint32_t a2, uint32_t a3, uint32_t b0, uint32_t b1) {
    asm volatile("mma.sync.aligned.m16n8k16.row.col.f32.bf16.bf16.f32 "
                 "{%0,%1,%2,%3}, {%4,%5,%6,%7}, {%8,%9}, {%0,%1,%2,%3};"
                 : "+f"(d[0]), "+f"(d[1]), "+f"(d[2]), "+f"(d[3])
                 : "r"(a0), "r"(a1), "r"(a2), "r"(a3), "r"(b0), "r"(b1));
}
__device__ __forceinline__ uint32_t pk2(float a, float b) {
    return (uint32_t)__bfloat16_as_ushort(__float2bfloat16_rn(a)) |
           ((uint32_t)__bfloat16_as_ushort(__float2bfloat16_rn(b)) << 16);
}
__device__ __forceinline__ float blo(float v) {
    return v - __bfloat162float(__float2bfloat16_rn(v));
}

// ---------------- weight prep ----------------
// builds g_wfc_t and the fragment-order conv weight arrays
__global__ void k_prep(const float* __restrict__ Wfc,
                       const float* __restrict__ W1,
                       const float* __restrict__ W2) {
    int i = blockIdx.x * blockDim.x + threadIdx.x;
    if (i < 3*C*C) {
        int c = i >> 6, oc = i & 63;
        g_wfc_t[i] = Wfc[oc * (3*C) + c];
    }
    if (i < 9*12*4*32) {                 // 13824
        int lane = i & 31;
        int np = (i >> 5) & 3;
        int jj = (i >> 7) % 12;
        int s  = (i >> 7) / 12;
        const int b_offs[12] = {0,16,32,48, 0,16,32,48, 64,80,96,112};

        auto valf = [&](const float* Wp, int oc, int cidx) -> float {
            if (cidx < 64) {
                return __bfloat162float(__float2bfloat16_rn(Wp[(oc*C + cidx)*9 + s]));
            } else {
                float w = Wp[(oc*C + (cidx - 64))*9 + s];
                return w - __bfloat162float(__float2bfloat16_rn(w));
            }
        };

        uint32_t r1[4], r2[4];
        #pragma unroll
        for (int u = 0; u < 4; u++) {
            int f = np*2 + (u >> 1);         // n8 fragment index 0..7
            int b = u & 1;                   // b0 / b1
            int n   = f*8 + (lane >> 2);     // oc
            int ci0 = b_offs[jj] + (lane & 3)*2 + b*8;
            r1[u] = pk2(valf(W1, n, ci0), valf(W1, n, ci0 + 1));
            r2[u] = pk2(valf(W2, n, ci0), valf(W2, n, ci0 + 1));
        }
        g_w1fr[i] = make_uint4(r1[0], r1[1], r1[2], r1[3]);
        g_w2fr[i] = make_uint4(r2[0], r2[1], r2[2], r2[3]);
    }
}

// ---------------- bilinear ----------------
struct Samp { int o00, o01, o10, o11; float w00, w01, w10, w11; };
__device__ __forceinline__ Samp make_samp(float gx, float gy) {
    float x0f = floorf(gx), y0f = floorf(gy);
    float wx = gx - x0f, wy = gy - y0f;
    int x0 = (int)x0f, y0 = (int)y0f, x1 = x0 + 1, y1 = y0 + 1;
    bool vx0 = (x0>=0)&&(x0<W), vx1 = (x1>=0)&&(x1<W);
    bool vy0 = (y0>=0)&&(y0<H), vy1 = (y1>=0)&&(y1<H);
    int cx0 = min(max(x0,0),W-1), cx1 = min(max(x1,0),W-1);
    int cy0 = min(max(y0,0),H-1), cy1 = min(max(y1,0),H-1);
    Samp s;
    s.o00 = cy0*W+cx0; s.o01 = cy0*W+cx1; s.o10 = cy1*W+cx0; s.o11 = cy1*W+cx1;
    s.w00 = (vx0&&vy0) ? (1.f-wx)*(1.f-wy) : 0.f;
    s.w01 = (vx1&&vy0) ? wx*(1.f-wy)       : 0.f;
    s.w10 = (vx0&&vy1) ? (1.f-wx)*wy       : 0.f;
    s.w11 = (vx1&&vy1) ? wx*wy             : 0.f;
    return s;
}
__device__ __forceinline__ float bsample(const float* __restrict__ p, const Samp& s) {
    return p[s.o00]*s.w00 + p[s.o01]*s.w01 + p[s.o10]*s.w10 + p[s.o11]*s.w11;
}

// ---------------- kernel 1: fused warp + 1x1 conv, split-bf16 row epilogue ----------------
__global__ __launch_bounds__(128) void k_wfc(
    const float* __restrict__ feats, const float* __restrict__ flows,
    const float* __restrict__ out,   const float* __restrict__ bfc, int t)
{
    __shared__ float sin[2*C][32];
    __shared__ Samp ss1[32], ss2[32];

    int bid = blockIdx.x;
    int n = bid >> 9, rem = bid & 511;
    int y = rem >> 2, x0 = (rem & 3) * 32;
    int tid = threadIdx.x;

    const float* y1p = (t >= 1) ? out   + (size_t)(n*T + (t-1)) * C * HW
                                : feats + (size_t)(n*T)         * C * HW;
    const float* y2p = (t >= 2) ? out   + (size_t)(n*T + (t-2)) * C * HW
                                : feats + (size_t)(n*T)         * C * HW;

    if (tid < 32) {
        int x = x0 + tid, pix = y * W + x;
        float f1x = 0.f, f1y = 0.f;
        if (t >= 1) {
            const float* f1p = flows + (size_t)(n*T + (t-1)) * 2 * HW;
            f1x = f1p[pix]; f1y = f1p[HW + pix];
        }
        Samp s1 = make_samp((float)x + f1x, (float)y + f1y);
        float f2cx = f1x, f2cy = f1y;
        if (t >= 2) {
            const float* f2p = flows + (size_t)(n*T + (t-2)) * 2 * HW;
            f2cx += bsample(f2p, s1);
            f2cy += bsample(f2p + HW, s1);
        }
        ss1[tid] = s1;
        ss2[tid] = make_samp((float)x + f2cx, (float)y + f2cy);
    }
    __syncthreads();
    {
        int px = tid & 31, cg = tid >> 5;
        Samp s1 = ss1[px], s2 = ss2[px];
        int c0 = cg * 16;
        #pragma unroll 4
        for (int ci = c0; ci < c0 + 16; ci++) {
            sin[ci][px]     = bsample(y2p + (size_t)ci*HW, s2);
            sin[C + ci][px] = bsample(y1p + (size_t)ci*HW, s1);
        }
    }
    __syncthreads();

    int tx = tid & 7, og = tid >> 3;
    const float* xb = feats + (size_t)(n*T + t) * C * HW + y*W + x0;

    float4 acc[4];
    #pragma unroll
    for (int o = 0; o < 4; o++) {
        float b = __ldg(bfc + og*4 + o);
        acc[o] = make_float4(b, b, b, b);
    }
    #pragma unroll 4
    for (int c = 0; c < 2*C; c++) {
        float4 v = *((const float4*)&sin[c][0] + tx);
        float4 wv = __ldg((const float4*)(g_wfc_t + (size_t)c * C) + og);
        float wo[4] = {wv.x, wv.y, wv.z, wv.w};
        #pragma unroll
        for (int o = 0; o < 4; o++) {
            acc[o].x += v.x*wo[o]; acc[o].y += v.y*wo[o];
            acc[o].z += v.z*wo[o]; acc[o].w += v.w*wo[o];
        }
    }
    #pragma unroll 4
    for (int c = 0; c < C; c++) {
        float4 v = __ldg((const float4*)(xb + (size_t)c*HW) + tx);
        float4 wv = __ldg((const float4*)(g_wfc_t + (size_t)(2*C + c) * C) + og);
        float wo[4] = {wv.x, wv.y, wv.z, wv.w};
        #pragma unroll
        for (int o = 0; o < 4; o++) {
            acc[o].x += v.x*wo[o]; acc[o].y += v.y*wo[o];
            acc[o].z += v.z*wo[o]; acc[o].w += v.w*wo[o];
        }
    }

    float vj[4][4] = {
        {acc[0].x, acc[1].x, acc[2].x, acc[3].x},
        {acc[0].y, acc[1].y, acc[2].y, acc[3].y},
        {acc[0].z, acc[1].z, acc[2].z, acc[3].z},
        {acc[0].w, acc[1].w, acc[2].w, acc[3].w}};
    #pragma unroll
    for (int j = 0; j < 4; j++) {
        bf16* row = g_fbuf + ((size_t)(n*H + y)*W + x0 + 4*tx + j) * 128;
        float v0 = vj[j][0], v1 = vj[j][1], v2 = vj[j][2], v3 = vj[j][3];
        *((uint2*)(row + og*4))      = make_uint2(pk2(v0, v1), pk2(v2, v3));
        *((uint2*)(row + 64 + og*4)) = make_uint2(pk2(blo(v0), blo(v1)), pk2(blo(v2), blo(v3)));
    }
}

// ---------------- 3x3 conv via mma.sync bf16, B fragments direct from gmem ----------
// grid (2, 128, NB), block 256 (8 warps); CTA = 64-px strip x 64 oc
// warp: px group pg = warp>>1 (16 px), oc half oh = warp&1 (32 oc)
#define AROW 136
#define ASZ  (3*66*AROW)
#define SMEM_CONV (ASZ * 2)      // 53856 B (A only; epilogue reuses as Ds)

__global__ __launch_bounds__(256) void k_conv_mma(
    float* __restrict__ outp, const float* __restrict__ bias,
    const float* __restrict__ feats, int phase, int t)
{
    extern __shared__ __align__(16) uint8_t smraw[];
    bf16*  As = (bf16*)smraw;              // [3][66][AROW]
    float* Ds = (float*)smraw;             // epilogue reuse: [64][66]

    int tid = threadIdx.x, lane = tid & 31, warp = tid >> 5;
    int pg = warp >> 1, oh = warp & 1;
    int n = blockIdx.z, y = blockIdx.y, x0 = blockIdx.x * 64;

    const bf16* act  = phase ? g_hbuf : g_fbuf;
    const uint4* wfr = phase ? g_w2fr : g_w1fr;

    // ---- stage A: rows y-1..y+1, cols x0-1..x0+64, 128 bf16 each ----
    for (int i = tid; i < 3*66*16; i += 256) {
        int u = i & 15, cc = (i >> 4) % 66, r = (i >> 4) / 66;
        int gy = y + r - 1, gx = x0 + cc - 1;
        uint4 v = make_uint4(0u, 0u, 0u, 0u);
        if (gy >= 0 && gy < H && gx >= 0 && gx < W)
            v = __ldg((const uint4*)(act + ((size_t)(n*H + gy)*W + gx)*128) + u);
        *((uint4*)(As + (r*66 + cc)*AROW) + u) = v;
    }
    __syncthreads();

    float ac[4][4];
    #pragma unroll
    for (int nf = 0; nf < 4; nf++) {
        ac[nf][0] = 0.f; ac[nf][1] = 0.f; ac[nf][2] = 0.f; ac[nf][3] = 0.f;
    }

    uint32_t as_u32 = smem_u32(As);
    int a_px = ((lane >> 3) & 1)*8 + (lane & 7);
    int a_k8 = (lane >> 4) * 8;
    const int a_offs[12] = {0,16,32,48, 64,80,96,112, 0,16,32,48};

    for (int s = 0; s < 9; s++) {
        int r = s / 3, dx = (s % 3) - 1;
        uint32_t abase = as_u32 +
            (uint32_t)((r*66 + pg*16 + a_px + dx + 1)*AROW + a_k8) * 2;
        const uint4* wbase = wfr + (size_t)(s*12)*4*32 + oh*2*32 + lane;

        #pragma unroll
        for (int j = 0; j < 12; j++) {
            uint32_t a0, a1, a2, a3;
            ldsm4(a0, a1, a2, a3, abase + a_offs[j]*2);
            uint4 b0 = __ldg(wbase + (size_t)j*4*32);
            uint4 b1 = __ldg(wbase + (size_t)j*4*32 + 32);
            mma16816(ac[0], a0, a1, a2, a3, b0.x, b0.y);
            mma16816(ac[1], a0, a1, a2, a3, b0.z, b0.w);
            mma16816(ac[2], a0, a1, a2, a3, b1.x, b1.y);
            mma16816(ac[3], a0, a1, a2, a3, b1.z, b1.w);
        }
    }

    __syncthreads();
    // ---- fragments -> Ds (bias + activation) ----
    int g = lane >> 2, tg = lane & 3;
    int pa = pg*16 + g, pb = pa + 8;
    #pragma unroll
    for (int nf = 0; nf < 4; nf++) {
        int oc = oh*32 + nf*8 + 2*tg;
        float bx = __ldg(bias + oc), by = __ldg(bias + oc + 1);
        float v0 = ac[nf][0] + bx, v1 = ac[nf][1] + by;
        float v2 = ac[nf][2] + bx, v3 = ac[nf][3] + by;
        if (phase == 0) {
            v0 = v0 > 0.f ? v0 : 0.1f*v0;  v1 = v1 > 0.f ? v1 : 0.1f*v1;
            v2 = v2 > 0.f ? v2 : 0.1f*v2;  v3 = v3 > 0.f ? v3 : 0.1f*v3;
        }
        Ds[pa*66 + oc] = v0;  Ds[pa*66 + oc + 1] = v1;
        Ds[pb*66 + oc] = v2;  Ds[pb*66 + oc + 1] = v3;
    }
    __syncthreads();

    if (phase == 0) {
        for (int i = tid; i < 64*16; i += 256) {
            int px = i >> 4, q = i & 15;
            const float* dv = Ds + px*66 + q*4;
            float v0 = dv[0], v1 = dv[1], v2 = dv[2], v3 = dv[3];
            bf16* row = g_hbuf + ((size_t)(n*H + y)*W + x0 + px) * 128;
            *((uint2*)(row + q*4))      = make_uint2(pk2(v0, v1), pk2(v2, v3));
            *((uint2*)(row + 64 + q*4)) = make_uint2(pk2(blo(v0), blo(v1)), pk2(blo(v2), blo(v3)));
        }
    } else {
        size_t base = (size_t)(n*T + t)*C*HW + (size_t)y*W + x0;
        for (int i = tid; i < 64*64; i += 256) {
            int oc = i >> 6, px = i & 63;
            size_t off = base + (size_t)oc*HW + px;
            outp[off] = Ds[px*66 + oc] + __ldg(feats + off);
        }
    }
}

// ---------------- launch ----------------
extern "C" void kernel_launch(void* const* d_in, const int* in_sizes, int n_in,
                              void* d_out, int out_size) {
    const float* feats = (const float*)d_in[0];
    const float* flows = (const float*)d_in[1];
    const float* bfc   = (const float*)d_in[3];
    const float* b1    = (const float*)d_in[5];
    const float* b2    = (const float*)d_in[7];
    float* out = (float*)d_out;
    (void)in_sizes; (void)n_in; (void)out_size;

    cudaFuncSetAttribute(k_conv_mma, cudaFuncAttributeMaxDynamicSharedMemorySize, SMEM_CONV);

    k_prep<<<(9*C*C + 255)/256, 256>>>((const float*)d_in[2],
                                       (const float*)d_in[4],
                                       (const float*)d_in[6]);

    dim3 mgrid(2, 128, NB);
    for (int t = 0; t < T; t++) {
        k_wfc<<<NB*512, 128>>>(feats, flows, out, bfc, t);
        k_conv_mma<<<mgrid, 256, SMEM_CONV>>>(out, b1, feats, 0, t);
        k_conv_mma<<<mgrid, 256, SMEM_CONV>>>(out, b2, feats, 1, t);
    }
}

// round 16
// speedup vs baseline: 1.1295x; 1.1295x over previous
#include <cuda_runtime.h>
#include <cuda_bf16.h>
#include <cstdint>

#define NB 2
#define T  16
#define C  64
#define H  128
#define W  128
#define HW (H*W)

typedef __nv_bfloat16 bf16;

// ---------------- scratch (no allocation allowed) ----------------
// activations: pixel-row-major, 128 bf16/pixel = [hi ch0..63 | lo ch0..63]
__device__ __align__(16) bf16 g_fbuf[(size_t)NB*H*W*128];   // 1x1-conv out (conv1 in)
__device__ __align__(16) bf16 g_hbuf[(size_t)NB*H*W*128];   // conv1 out (conv2 in)
__device__ float g_wfc_t[3*C*C];                            // [192][64] fp32
// conv weights: [shift s][oc][ whi(ci 0..63) | wlo(ci 0..63) ]
__device__ __align__(16) bf16 g_w1bf[9*C*128];
__device__ __align__(16) bf16 g_w2bf[9*C*128];

// ---------------- helpers ----------------
__device__ __forceinline__ uint32_t smem_u32(const void* p) {
    uint32_t a;
    asm("{ .reg .u64 t; cvta.to.shared.u64 t, %1; cvt.u32.u64 %0, t; }" : "=r"(a) : "l"(p));
    return a;
}
__device__ __forceinline__ void ldsm4(uint32_t& r0, uint32_t& r1, uint32_t& r2, uint32_t& r3,
                                      uint32_t addr) {
    asm volatile("ldmatrix.sync.aligned.m8n8.x4.shared.b16 {%0,%1,%2,%3}, [%4];"
                 : "=r"(r0), "=r"(r1), "=r"(r2), "=r"(r3) : "r"(addr));
}
__device__ __forceinline__ void mma16816(float* d,
        uint32_t a0, uint32_t a1, uint32_t a2, uint32_t a3, uint32_t b0, uint32_t b1) {
    asm volatile("mma.sync.aligned.m16n8k16.row.col.f32.bf16.bf16.f32 "
                 "{%0,%1,%2,%3}, {%4,%5,%6,%7}, {%8,%9}, {%0,%1,%2,%3};"
                 : "+f"(d[0]), "+f"(d[1]), "+f"(d[2]), "+f"(d[3])
                 : "r"(a0), "r"(a1), "r"(a2), "r"(a3), "r"(b0), "r"(b1));
}
__device__ __forceinline__ uint32_t pk2(float a, float b) {
    return (uint32_t)__bfloat16_as_ushort(__float2bfloat16_rn(a)) |
           ((uint32_t)__bfloat16_as_ushort(__float2bfloat16_rn(b)) << 16);
}
__device__ __forceinline__ float blo(float v) {
    return v - __bfloat162float(__float2bfloat16_rn(v));
}

// ---------------- weight prep ----------------
__global__ void k_prep(const float* __restrict__ Wfc,
                       const float* __restrict__ W1,
                       const float* __restrict__ W2) {
    int i = blockIdx.x * blockDim.x + threadIdx.x;
    if (i < 3*C*C) {
        int c = i >> 6, oc = i & 63;
        g_wfc_t[i] = Wfc[oc * (3*C) + c];
    }
    if (i < 9*C*C) {
        int s = i >> 12, r = i & 4095;
        int oc = r >> 6, ci = r & 63;
        float w1 = W1[(oc*C + ci)*9 + s];
        float w2 = W2[(oc*C + ci)*9 + s];
        bf16 h1 = __float2bfloat16_rn(w1), h2 = __float2bfloat16_rn(w2);
        g_w1bf[(size_t)s*8192 + oc*128 + ci]      = h1;
        g_w1bf[(size_t)s*8192 + oc*128 + 64 + ci] = __float2bfloat16_rn(w1 - __bfloat162float(h1));
        g_w2bf[(size_t)s*8192 + oc*128 + ci]      = h2;
        g_w2bf[(size_t)s*8192 + oc*128 + 64 + ci] = __float2bfloat16_rn(w2 - __bfloat162float(h2));
    }
}

// ---------------- bilinear ----------------
struct Samp { int o00, o01, o10, o11; float w00, w01, w10, w11; };
__device__ __forceinline__ Samp make_samp(float gx, float gy) {
    float x0f = floorf(gx), y0f = floorf(gy);
    float wx = gx - x0f, wy = gy - y0f;
    int x0 = (int)x0f, y0 = (int)y0f, x1 = x0 + 1, y1 = y0 + 1;
    bool vx0 = (x0>=0)&&(x0<W), vx1 = (x1>=0)&&(x1<W);
    bool vy0 = (y0>=0)&&(y0<H), vy1 = (y1>=0)&&(y1<H);
    int cx0 = min(max(x0,0),W-1), cx1 = min(max(x1,0),W-1);
    int cy0 = min(max(y0,0),H-1), cy1 = min(max(y1,0),H-1);
    Samp s;
    s.o00 = cy0*W+cx0; s.o01 = cy0*W+cx1; s.o10 = cy1*W+cx0; s.o11 = cy1*W+cx1;
    s.w00 = (vx0&&vy0) ? (1.f-wx)*(1.f-wy) : 0.f;
    s.w01 = (vx1&&vy0) ? wx*(1.f-wy)       : 0.f;
    s.w10 = (vx0&&vy1) ? (1.f-wx)*wy       : 0.f;
    s.w11 = (vx1&&vy1) ? wx*wy             : 0.f;
    return s;
}
__device__ __forceinline__ float bsample(const float* __restrict__ p, const Samp& s) {
    return p[s.o00]*s.w00 + p[s.o01]*s.w01 + p[s.o10]*s.w10 + p[s.o11]*s.w11;
}

// ---------------- kernel 1: fused warp + 1x1 conv, split-bf16 row epilogue ----------------
__global__ __launch_bounds__(128) void k_wfc(
    const float* __restrict__ feats, const float* __restrict__ flows,
    const float* __restrict__ out,   const float* __restrict__ bfc, int t)
{
    __shared__ float sin[2*C][32];
    __shared__ Samp ss1[32], ss2[32];

    int bid = blockIdx.x;
    int n = bid >> 9, rem = bid & 511;
    int y = rem >> 2, x0 = (rem & 3) * 32;
    int tid = threadIdx.x;

    const float* y1p = (t >= 1) ? out   + (size_t)(n*T + (t-1)) * C * HW
                                : feats + (size_t)(n*T)         * C * HW;
    const float* y2p = (t >= 2) ? out   + (size_t)(n*T + (t-2)) * C * HW
                                : feats + (size_t)(n*T)         * C * HW;

    if (tid < 32) {
        int x = x0 + tid, pix = y * W + x;
        float f1x = 0.f, f1y = 0.f;
        if (t >= 1) {
            const float* f1p = flows + (size_t)(n*T + (t-1)) * 2 * HW;
            f1x = f1p[pix]; f1y = f1p[HW + pix];
        }
        Samp s1 = make_samp((float)x + f1x, (float)y + f1y);
        float f2cx = f1x, f2cy = f1y;
        if (t >= 2) {
            const float* f2p = flows + (size_t)(n*T + (t-2)) * 2 * HW;
            f2cx += bsample(f2p, s1);
            f2cy += bsample(f2p + HW, s1);
        }
        ss1[tid] = s1;
        ss2[tid] = make_samp((float)x + f2cx, (float)y + f2cy);
    }
    __syncthreads();
    {
        int px = tid & 31, cg = tid >> 5;
        Samp s1 = ss1[px], s2 = ss2[px];
        int c0 = cg * 16;
        #pragma unroll 4
        for (int ci = c0; ci < c0 + 16; ci++) {
            sin[ci][px]     = bsample(y2p + (size_t)ci*HW, s2);
            sin[C + ci][px] = bsample(y1p + (size_t)ci*HW, s1);
        }
    }
    __syncthreads();

    int tx = tid & 7, og = tid >> 3;
    const float* xb = feats + (size_t)(n*T + t) * C * HW + y*W + x0;

    float4 acc[4];
    #pragma unroll
    for (int o = 0; o < 4; o++) {
        float b = __ldg(bfc + og*4 + o);
        acc[o] = make_float4(b, b, b, b);
    }
    #pragma unroll 4
    for (int c = 0; c < 2*C; c++) {
        float4 v = *((const float4*)&sin[c][0] + tx);
        float4 wv = __ldg((const float4*)(g_wfc_t + (size_t)c * C) + og);
        float wo[4] = {wv.x, wv.y, wv.z, wv.w};
        #pragma unroll
        for (int o = 0; o < 4; o++) {
            acc[o].x += v.x*wo[o]; acc[o].y += v.y*wo[o];
            acc[o].z += v.z*wo[o]; acc[o].w += v.w*wo[o];
        }
    }
    #pragma unroll 4
    for (int c = 0; c < C; c++) {
        float4 v = __ldg((const float4*)(xb + (size_t)c*HW) + tx);
        float4 wv = __ldg((const float4*)(g_wfc_t + (size_t)(2*C + c) * C) + og);
        float wo[4] = {wv.x, wv.y, wv.z, wv.w};
        #pragma unroll
        for (int o = 0; o < 4; o++) {
            acc[o].x += v.x*wo[o]; acc[o].y += v.y*wo[o];
            acc[o].z += v.z*wo[o]; acc[o].w += v.w*wo[o];
        }
    }

    float vj[4][4] = {
        {acc[0].x, acc[1].x, acc[2].x, acc[3].x},
        {acc[0].y, acc[1].y, acc[2].y, acc[3].y},
        {acc[0].z, acc[1].z, acc[2].z, acc[3].z},
        {acc[0].w, acc[1].w, acc[2].w, acc[3].w}};
    #pragma unroll
    for (int j = 0; j < 4; j++) {
        bf16* row = g_fbuf + ((size_t)(n*H + y)*W + x0 + 4*tx + j) * 128;
        float v0 = vj[j][0], v1 = vj[j][1], v2 = vj[j][2], v3 = vj[j][3];
        *((uint2*)(row + og*4))      = make_uint2(pk2(v0, v1), pk2(v2, v3));
        *((uint2*)(row + 64 + og*4)) = make_uint2(pk2(blo(v0), blo(v1)), pk2(blo(v2), blo(v3)));
    }
}

// ---------------- 3x3 conv via mma.sync bf16 (split 3-term), pipelined B staging ----
// grid (2, 128, NB), block 128 (4 warps); CTA = 64-px row strip x 64 oc
#define AROW 136
#define ASZ  (3*66*AROW)
#define BSZ  (64*AROW)
#define SMEM_CONV ((ASZ + BSZ) * 2)

__global__ __launch_bounds__(128, 3) void k_conv_mma(
    float* __restrict__ outp, const float* __restrict__ bias,
    const float* __restrict__ feats, int phase, int t)
{
    extern __shared__ __align__(16) uint8_t smraw[];
    bf16*  As = (bf16*)smraw;              // [3][66][AROW]
    bf16*  Bs = (bf16*)smraw + ASZ;        // [64][AROW]
    float* Ds = (float*)smraw;             // epilogue reuse: [64][66]

    int tid = threadIdx.x, lane = tid & 31, warp = tid >> 5;
    int n = blockIdx.z, y = blockIdx.y, x0 = blockIdx.x * 64;

    const bf16* act  = phase ? g_hbuf : g_fbuf;
    const bf16* wsrc = phase ? g_w2bf : g_w1bf;

    // ---- stage A (rows y-1..y+1, cols x0-1..x0+64) + B shift 0, one sync ----
    for (int i = tid; i < 3*66*16; i += 128) {
        int u = i & 15, cc = (i >> 4) % 66, r = (i >> 4) / 66;
        int gy = y + r - 1, gx = x0 + cc - 1;
        uint4 v = make_uint4(0u, 0u, 0u, 0u);
        if (gy >= 0 && gy < H && gx >= 0 && gx < W)
            v = __ldg((const uint4*)(act + ((size_t)(n*H + gy)*W + gx)*128) + u);
        *((uint4*)(As + (r*66 + cc)*AROW) + u) = v;
    }
    #pragma unroll
    for (int q = 0; q < 8; q++) {
        int i = tid + q*128;
        int u = i & 15, oc = i >> 4;
        *((uint4*)(Bs + oc*AROW) + u) = __ldg((const uint4*)(wsrc + (size_t)oc*128) + u);
    }
    __syncthreads();

    float ac[8][4];
    #pragma unroll
    for (int nf = 0; nf < 8; nf++) {
        ac[nf][0] = 0.f; ac[nf][1] = 0.f; ac[nf][2] = 0.f; ac[nf][3] = 0.f;
    }

    uint32_t as_u32 = smem_u32(As);
    uint32_t bs_u32 = smem_u32(Bs);
    int a_px = ((lane >> 3) & 1)*8 + (lane & 7);
    int a_k8 = (lane >> 4) * 8;
    int b_oc = ((lane >> 4) & 1)*8 + (lane & 7);
    int b_k8 = ((lane >> 3) & 1)*8;
    uint32_t bbase = bs_u32 + (uint32_t)(b_oc*AROW + b_k8) * 2;

    for (int s = 0; s < 9; s++) {
        // prefetch next shift's B into regs (no consumer until after compute)
        uint4 pre[8];
        if (s < 8) {
            #pragma unroll
            for (int q = 0; q < 8; q++) {
                int i = tid + q*128;
                int u = i & 15, oc = i >> 4;
                pre[q] = __ldg((const uint4*)(wsrc + ((size_t)(s+1)*64 + oc)*128) + u);
            }
        }

        int r = s / 3, dx = (s % 3) - 1;
        uint32_t abase = as_u32 +
            (uint32_t)((r*66 + warp*16 + a_px + dx + 1)*AROW + a_k8) * 2;

        uint32_t ah[4][4];                 // cached A_hi fragments (reused part 3)
        // part 1: A_hi x B_hi
        #pragma unroll
        for (int jj = 0; jj < 4; jj++) {
            ldsm4(ah[jj][0], ah[jj][1], ah[jj][2], ah[jj][3], abase + (jj*16)*2);
            #pragma unroll
            for (int e2 = 0; e2 < 4; e2++) {
                uint32_t b0, b1, b2, b3;
                ldsm4(b0, b1, b2, b3, bbase + (e2*16*AROW + jj*16)*2);
                mma16816(ac[2*e2],     ah[jj][0], ah[jj][1], ah[jj][2], ah[jj][3], b0, b1);
                mma16816(ac[2*e2 + 1], ah[jj][0], ah[jj][1], ah[jj][2], ah[jj][3], b2, b3);
            }
        }
        // part 2: A_lo x B_hi
        #pragma unroll
        for (int jj = 0; jj < 4; jj++) {
            uint32_t a0, a1, a2, a3;
            ldsm4(a0, a1, a2, a3, abase + (64 + jj*16)*2);
            #pragma unroll
            for (int e2 = 0; e2 < 4; e2++) {
                uint32_t b0, b1, b2, b3;
                ldsm4(b0, b1, b2, b3, bbase + (e2*16*AROW + jj*16)*2);
                mma16816(ac[2*e2],     a0, a1, a2, a3, b0, b1);
                mma16816(ac[2*e2 + 1], a0, a1, a2, a3, b2, b3);
            }
        }
        // part 3: A_hi (cached) x B_lo
        #pragma unroll
        for (int jj = 0; jj < 4; jj++) {
            #pragma unroll
            for (int e2 = 0; e2 < 4; e2++) {
                uint32_t b0, b1, b2, b3;
                ldsm4(b0, b1, b2, b3, bbase + (e2*16*AROW + 64 + jj*16)*2);
                mma16816(ac[2*e2],     ah[jj][0], ah[jj][1], ah[jj][2], ah[jj][3], b0, b1);
                mma16816(ac[2*e2 + 1], ah[jj][0], ah[jj][1], ah[jj][2], ah[jj][3], b2, b3);
            }
        }

        __syncthreads();
        if (s < 8) {
            #pragma unroll
            for (int q = 0; q < 8; q++) {
                int i = tid + q*128;
                int u = i & 15, oc = i >> 4;
                *((uint4*)(Bs + oc*AROW) + u) = pre[q];
            }
            __syncthreads();
        }
    }

    // ---- fragments -> Ds (bias + activation), then coalesced writeout ----
    int g = lane >> 2, tg = lane & 3;
    int pa = warp*16 + g, pb = pa + 8;
    #pragma unroll
    for (int nf = 0; nf < 8; nf++) {
        int oc = nf*8 + 2*tg;
        float bx = __ldg(bias + oc), by = __ldg(bias + oc + 1);
        float v0 = ac[nf][0] + bx, v1 = ac[nf][1] + by;
        float v2 = ac[nf][2] + bx, v3 = ac[nf][3] + by;
        if (phase == 0) {
            v0 = v0 > 0.f ? v0 : 0.1f*v0;  v1 = v1 > 0.f ? v1 : 0.1f*v1;
            v2 = v2 > 0.f ? v2 : 0.1f*v2;  v3 = v3 > 0.f ? v3 : 0.1f*v3;
        }
        Ds[pa*66 + oc] = v0;  Ds[pa*66 + oc + 1] = v1;
        Ds[pb*66 + oc] = v2;  Ds[pb*66 + oc + 1] = v3;
    }
    __syncthreads();

    if (phase == 0) {
        for (int i = tid; i < 64*16; i += 128) {
            int px = i >> 4, q = i & 15;
            const float* dv = Ds + px*66 + q*4;
            float v0 = dv[0], v1 = dv[1], v2 = dv[2], v3 = dv[3];
            bf16* row = g_hbuf + ((size_t)(n*H + y)*W + x0 + px) * 128;
            *((uint2*)(row + q*4))      = make_uint2(pk2(v0, v1), pk2(v2, v3));
            *((uint2*)(row + 64 + q*4)) = make_uint2(pk2(blo(v0), blo(v1)), pk2(blo(v2), blo(v3)));
        }
    } else {
        size_t base = (size_t)(n*T + t)*C*HW + (size_t)y*W + x0;
        for (int i = tid; i < 64*64; i += 128) {
            int oc = i >> 6, px = i & 63;
            size_t off = base + (size_t)oc*HW + px;
            outp[off] = Ds[px*66 + oc] + __ldg(feats + off);
        }
    }
}

// ---------------- launch ----------------
extern "C" void kernel_launch(void* const* d_in, const int* in_sizes, int n_in,
                              void* d_out, int out_size) {
    const float* feats = (const float*)d_in[0];
    const float* flows = (const float*)d_in[1];
    const float* bfc   = (const float*)d_in[3];
    const float* b1    = (const float*)d_in[5];
    const float* b2    = (const float*)d_in[7];
    float* out = (float*)d_out;
    (void)in_sizes; (void)n_in; (void)out_size;

    cudaFuncSetAttribute(k_conv_mma, cudaFuncAttributeMaxDynamicSharedMemorySize, SMEM_CONV);

    k_prep<<<(9*C*C + 255)/256, 256>>>((const float*)d_in[2],
                                       (const float*)d_in[4],
                                       (const float*)d_in[6]);

    dim3 mgrid(2, 128, NB);
    for (int t = 0; t < T; t++) {
        k_wfc<<<NB*512, 128>>>(feats, flows, out, bfc, t);
        k_conv_mma<<<mgrid, 128, SMEM_CONV>>>(out, b1, feats, 0, t);
        k_conv_mma<<<mgrid, 128, SMEM_CONV>>>(out, b2, feats, 1, t);
    }
}